// round 1
// baseline (speedup 1.0000x reference)
#include <cuda_runtime.h>

// Problem constants (fixed by the dataset)
#define NN    50000
#define EE    800000
#define INC   128
#define HEADS 8
#define HID   32
#define C1    256          // HEADS*HID
#define OUTC  16
#define NEG   0.2f
#define EPSV  1e-16f

// ---------------- scratch (static device globals; no allocation) ----------------
__device__ float g_xl1[NN * C1];       // layer1 linear output  [N,256]
__device__ float g_h1 [NN * C1];       // elu(gat1) output      [N,256]
__device__ float g_as1[NN * HEADS];    // per-node src logits   [N,8]
__device__ float g_ad1[NN * HEADS];    // per-node dst logits   [N,8]
__device__ float g_xl2[NN * OUTC];     // layer2 linear output  [N,16]
__device__ float g_as2[NN];
__device__ float g_ad2[NN];
__device__ int   g_deg[NN];
__device__ int   g_rowptr[NN + 1];
__device__ int   g_cursor[NN];
__device__ int   g_col[EE];            // CSR (by dst) source node ids

// ---------------- CSR build ----------------
__global__ void zero_deg_kernel() {
    int i = blockIdx.x * blockDim.x + threadIdx.x;
    for (; i < NN; i += gridDim.x * blockDim.x) g_deg[i] = 0;
}

__global__ void hist_kernel(const int* __restrict__ ei) {
    int i = blockIdx.x * blockDim.x + threadIdx.x;
    if (i < EE) atomicAdd(&g_deg[ei[EE + i]], 1);
}

// single block, 1024 threads: chunked sequential scan + block scan
__global__ void scan_kernel() {
    __shared__ int ssum[1024];
    const int T = 1024;
    int t = threadIdx.x;
    int chunk = (NN + T - 1) / T;                 // 49
    int b = t * chunk;
    int e = b + chunk; if (e > NN) e = NN;
    int s = 0;
    for (int i = b; i < e; i++) s += g_deg[i];
    ssum[t] = s;
    __syncthreads();
    for (int off = 1; off < T; off <<= 1) {
        int v = (t >= off) ? ssum[t - off] : 0;
        __syncthreads();
        ssum[t] += v;
        __syncthreads();
    }
    int offset = (t == 0) ? 0 : ssum[t - 1];
    if (t == 0) g_rowptr[0] = 0;
    int run = offset;
    for (int i = b; i < e; i++) {
        g_cursor[i] = run;
        run += g_deg[i];
        g_rowptr[i + 1] = run;
    }
}

__global__ void scatter_kernel(const int* __restrict__ ei) {
    int i = blockIdx.x * blockDim.x + threadIdx.x;
    if (i < EE) {
        int d = ei[EE + i];
        int pos = atomicAdd(&g_cursor[d], 1);
        g_col[pos] = ei[i];
    }
}

// ---------------- GEMM1: x[N,128] @ W1[128,256] -> g_xl1 ----------------
#define BM 64
#define BN 64
#define BK 16
__global__ void gemm1_kernel(const float* __restrict__ A, const float* __restrict__ B) {
    __shared__ float As[BK][BM];
    __shared__ float Bs[BK][BN];
    int tid = threadIdx.x;                 // 256 threads
    int bm = blockIdx.x * BM;
    int bn = blockIdx.y * BN;
    int trow = (tid >> 4) << 2;            // 0..60
    int tcol = (tid & 15) << 2;            // 0..60
    float acc[4][4];
#pragma unroll
    for (int i = 0; i < 4; i++)
#pragma unroll
        for (int j = 0; j < 4; j++) acc[i][j] = 0.f;

    int arow = tid >> 2;                   // 0..63
    int acol = (tid & 3) << 2;             // 0,4,8,12
    int brow = tid >> 4;                   // 0..15
    int bcol = (tid & 15) << 2;

    for (int k0 = 0; k0 < INC; k0 += BK) {
        float4 av = make_float4(0.f, 0.f, 0.f, 0.f);
        if (bm + arow < NN)
            av = *(const float4*)(A + (size_t)(bm + arow) * INC + k0 + acol);
        As[acol + 0][arow] = av.x;
        As[acol + 1][arow] = av.y;
        As[acol + 2][arow] = av.z;
        As[acol + 3][arow] = av.w;
        float4 bv = *(const float4*)(B + (size_t)(k0 + brow) * C1 + bn + bcol);
        *(float4*)&Bs[brow][bcol] = bv;
        __syncthreads();
#pragma unroll
        for (int k = 0; k < BK; k++) {
            float4 a = *(float4*)&As[k][trow];
            float4 bq = *(float4*)&Bs[k][tcol];
            float ar[4] = {a.x, a.y, a.z, a.w};
            float br[4] = {bq.x, bq.y, bq.z, bq.w};
#pragma unroll
            for (int i = 0; i < 4; i++)
#pragma unroll
                for (int j = 0; j < 4; j++) acc[i][j] += ar[i] * br[j];
        }
        __syncthreads();
    }
#pragma unroll
    for (int i = 0; i < 4; i++) {
        int row = bm + trow + i;
        if (row < NN) {
            float4 v = make_float4(acc[i][0], acc[i][1], acc[i][2], acc[i][3]);
            *(float4*)(g_xl1 + (size_t)row * C1 + bn + tcol) = v;
        }
    }
}

// ---------------- per-node logits layer1 ----------------
__global__ void logits1_kernel(const float* __restrict__ att_s, const float* __restrict__ att_d) {
    int gid = blockIdx.x * blockDim.x + threadIdx.x;
    if (gid >= NN * HEADS) return;
    int h = gid & 7;
    int node = gid >> 3;
    const float* p  = g_xl1 + (size_t)node * C1 + h * HID;
    const float* sa = att_s + h * HID;
    const float* da = att_d + h * HID;
    float s_acc = 0.f, d_acc = 0.f;
#pragma unroll
    for (int j = 0; j < HID; j += 4) {
        float4 v = *(const float4*)(p + j);
        float4 a = *(const float4*)(sa + j);
        float4 b = *(const float4*)(da + j);
        s_acc += v.x * a.x + v.y * a.y + v.z * a.z + v.w * a.w;
        d_acc += v.x * b.x + v.y * b.y + v.z * b.z + v.w * b.w;
    }
    g_as1[gid] = s_acc;
    g_ad1[gid] = d_acc;
}

__device__ __forceinline__ float lrelu(float x) { return x > 0.f ? x : NEG * x; }

// ---------------- aggregation layer1: warp per dst node ----------------
__global__ void agg1_kernel(const float* __restrict__ b1) {
    int warp = (blockIdx.x * blockDim.x + threadIdx.x) >> 5;
    if (warp >= NN) return;
    int lane = threadIdx.x & 31;
    int node = warp;
    int start = g_rowptr[node];
    int end   = g_rowptr[node + 1];

    float adst[HEADS], eself[HEADS], m[HEADS];
#pragma unroll
    for (int h = 0; h < HEADS; h++) {
        adst[h] = g_ad1[node * HEADS + h];
        eself[h] = lrelu(g_as1[node * HEADS + h] + adst[h]);
        m[h] = eself[h];
    }
    // pass A: max
    for (int idx = start + lane; idx < end; idx += 32) {
        int s = g_col[idx];
        const float4* ap = (const float4*)(g_as1 + (size_t)s * HEADS);
        float4 a0 = ap[0], a1 = ap[1];
        float av[8] = {a0.x, a0.y, a0.z, a0.w, a1.x, a1.y, a1.z, a1.w};
#pragma unroll
        for (int h = 0; h < HEADS; h++) {
            float e = lrelu(av[h] + adst[h]);
            m[h] = fmaxf(m[h], e);
        }
    }
#pragma unroll
    for (int h = 0; h < HEADS; h++)
#pragma unroll
        for (int o = 16; o; o >>= 1) m[h] = fmaxf(m[h], __shfl_xor_sync(0xffffffffu, m[h], o));

    // pass B: sum of exp
    float ssum[HEADS];
#pragma unroll
    for (int h = 0; h < HEADS; h++) ssum[h] = (lane == 0) ? __expf(eself[h] - m[h]) : 0.f;
    for (int idx = start + lane; idx < end; idx += 32) {
        int s = g_col[idx];
        const float4* ap = (const float4*)(g_as1 + (size_t)s * HEADS);
        float4 a0 = ap[0], a1 = ap[1];
        float av[8] = {a0.x, a0.y, a0.z, a0.w, a1.x, a1.y, a1.z, a1.w};
#pragma unroll
        for (int h = 0; h < HEADS; h++) {
            float e = lrelu(av[h] + adst[h]);
            ssum[h] += __expf(e - m[h]);
        }
    }
#pragma unroll
    for (int h = 0; h < HEADS; h++)
#pragma unroll
        for (int o = 16; o; o >>= 1) ssum[h] += __shfl_xor_sync(0xffffffffu, ssum[h], o);

    float inv[HEADS];
#pragma unroll
    for (int h = 0; h < HEADS; h++) inv[h] = 1.f / (ssum[h] + EPSV);

    // extract this lane's head scalars (avoid runtime-indexed register arrays)
    int myh = lane >> 2;
    float mh = 0.f, invh = 0.f, adh = 0.f, esh = 0.f;
#pragma unroll
    for (int h = 0; h < HEADS; h++) {
        if (h == myh) { mh = m[h]; invh = inv[h]; adh = adst[h]; esh = eself[h]; }
    }

    // pass C: weighted feature aggregation. lane covers channels [lane*8, lane*8+8)
    int c0 = lane * 8;
    float acc[8];
    {
        float a = __expf(esh - mh) * invh;
        const float4* xp = (const float4*)(g_xl1 + (size_t)node * C1 + c0);
        float4 v0 = xp[0], v1 = xp[1];
        acc[0] = a * v0.x; acc[1] = a * v0.y; acc[2] = a * v0.z; acc[3] = a * v0.w;
        acc[4] = a * v1.x; acc[5] = a * v1.y; acc[6] = a * v1.z; acc[7] = a * v1.w;
    }
    for (int idx = start; idx < end; idx++) {
        int s = g_col[idx];
        float e = lrelu(g_as1[(size_t)s * HEADS + myh] + adh);
        float a = __expf(e - mh) * invh;
        const float4* xp = (const float4*)(g_xl1 + (size_t)s * C1 + c0);
        float4 v0 = xp[0], v1 = xp[1];
        acc[0] += a * v0.x; acc[1] += a * v0.y; acc[2] += a * v0.z; acc[3] += a * v0.w;
        acc[4] += a * v1.x; acc[5] += a * v1.y; acc[6] += a * v1.z; acc[7] += a * v1.w;
    }
    // bias + ELU, store h1
    float4 o0, o1;
    float ov[8];
#pragma unroll
    for (int j = 0; j < 8; j++) {
        float v = acc[j] + b1[c0 + j];
        ov[j] = v > 0.f ? v : (__expf(v) - 1.f);
    }
    o0 = make_float4(ov[0], ov[1], ov[2], ov[3]);
    o1 = make_float4(ov[4], ov[5], ov[6], ov[7]);
    float4* hp = (float4*)(g_h1 + (size_t)node * C1 + c0);
    hp[0] = o0; hp[1] = o1;
}

// ---------------- GEMM2 + logits2: h[N,256] @ W2[256,16], fused logits ----------------
__global__ void gemm2_kernel(const float* __restrict__ W2,
                             const float* __restrict__ att_s2,
                             const float* __restrict__ att_d2) {
    __shared__ float Ws[256 * 16];
    __shared__ float Hs[16 * 256];
    __shared__ float sa[16], sd[16];
    int tid = threadIdx.x;                 // 256 threads, 16 rows per block
    for (int i = tid; i < 4096; i += 256) Ws[i] = W2[i];
    if (tid < 16) { sa[tid] = att_s2[tid]; sd[tid] = att_d2[tid]; }
    int base = blockIdx.x * 16;
    for (int i = tid; i < 4096; i += 256) {
        int r = i >> 8, k = i & 255;
        int row = base + r;
        Hs[i] = (row < NN) ? g_h1[(size_t)row * C1 + k] : 0.f;
    }
    __syncthreads();
    int r = tid >> 4, c = tid & 15;
    int row = base + r;
    float acc = 0.f;
#pragma unroll 8
    for (int k = 0; k < 256; k++) acc += Hs[r * 256 + k] * Ws[k * 16 + c];
    if (row < NN) g_xl2[(size_t)row * OUTC + c] = acc;
    float vs = acc * sa[c];
    float vd = acc * sd[c];
#pragma unroll
    for (int o = 8; o; o >>= 1) {
        vs += __shfl_xor_sync(0xffffffffu, vs, o, 16);
        vd += __shfl_xor_sync(0xffffffffu, vd, o, 16);
    }
    if (c == 0 && row < NN) { g_as2[row] = vs; g_ad2[row] = vd; }
}

// ---------------- aggregation layer2: warp per dst node, 16 channels ----------------
__global__ void agg2_kernel(const float* __restrict__ b2, float* __restrict__ out) {
    int warp = (blockIdx.x * blockDim.x + threadIdx.x) >> 5;
    if (warp >= NN) return;
    int lane = threadIdx.x & 31;
    int node = warp;
    int start = g_rowptr[node];
    int end   = g_rowptr[node + 1];

    float adst = g_ad2[node];
    float es = lrelu(g_as2[node] + adst);
    float m = es;
    for (int idx = start + lane; idx < end; idx += 32) {
        float e = lrelu(g_as2[g_col[idx]] + adst);
        m = fmaxf(m, e);
    }
#pragma unroll
    for (int o = 16; o; o >>= 1) m = fmaxf(m, __shfl_xor_sync(0xffffffffu, m, o));
    float ss = (lane == 0) ? __expf(es - m) : 0.f;
    for (int idx = start + lane; idx < end; idx += 32) {
        float e = lrelu(g_as2[g_col[idx]] + adst);
        ss += __expf(e - m);
    }
#pragma unroll
    for (int o = 16; o; o >>= 1) ss += __shfl_xor_sync(0xffffffffu, ss, o);
    float inv = 1.f / (ss + EPSV);

    int c = lane & 15;
    int half = lane >> 4;
    float acc = 0.f;
    if (half == 0) acc = __expf(es - m) * inv * g_xl2[(size_t)node * OUTC + c];
    for (int idx = start + half; idx < end; idx += 2) {
        int s = g_col[idx];
        float e = lrelu(g_as2[s] + adst);
        float a = __expf(e - m) * inv;
        acc += a * g_xl2[(size_t)s * OUTC + c];
    }
    acc += __shfl_down_sync(0xffffffffu, acc, 16);
    if (lane < 16) out[(size_t)node * OUTC + c] = acc + b2[c];
}

// ---------------- launch ----------------
extern "C" void kernel_launch(void* const* d_in, const int* in_sizes, int n_in,
                              void* d_out, int out_size) {
    const float* x     = (const float*)d_in[0];
    const int*   ei    = (const int*)d_in[1];
    const float* W1    = (const float*)d_in[2];
    const float* atts1 = (const float*)d_in[3];
    const float* attd1 = (const float*)d_in[4];
    const float* b1    = (const float*)d_in[5];
    const float* W2    = (const float*)d_in[6];
    const float* atts2 = (const float*)d_in[7];
    const float* attd2 = (const float*)d_in[8];
    const float* b2    = (const float*)d_in[9];
    float* out = (float*)d_out;

    zero_deg_kernel<<<64, 256>>>();
    hist_kernel<<<(EE + 255) / 256, 256>>>(ei);
    scan_kernel<<<1, 1024>>>();
    scatter_kernel<<<(EE + 255) / 256, 256>>>(ei);

    gemm1_kernel<<<dim3((NN + BM - 1) / BM, C1 / BN), 256>>>(x, W1);
    logits1_kernel<<<(NN * HEADS + 255) / 256, 256>>>(atts1, attd1);
    agg1_kernel<<<(NN + 7) / 8, 256>>>(b1);
    gemm2_kernel<<<(NN + 15) / 16, 256>>>(W2, atts2, attd2);
    agg2_kernel<<<(NN + 7) / 8, 256>>>(b2, out);
}

// round 3
// speedup vs baseline: 1.0944x; 1.0944x over previous
#include <cuda_runtime.h>

// Problem constants
#define NN    50000
#define EE    800000
#define INC   128
#define HEADS 8
#define HID   32
#define C1    256
#define OUTC  16
#define NEG   0.2f
#define EPSV  1e-16f

// ---------------- scratch ----------------
__device__ float g_xl1[NN * C1];
__device__ float g_h1 [NN * C1];
__device__ float g_as1[NN * HEADS];
__device__ float g_ad1[NN * HEADS];
__device__ float g_e  [EE * HEADS];    // per-edge exp(leakyrelu) per head
__device__ float g_xl2[NN * OUTC];
__device__ float g_as2[NN];
__device__ float g_ad2[NN];
__device__ int   g_deg[NN];
__device__ int   g_rowptr[NN + 1];
__device__ int   g_cursor[NN];
__device__ int   g_col[EE];

// ---------------- CSR build ----------------
__global__ void zero_deg_kernel() {
    int i = blockIdx.x * blockDim.x + threadIdx.x;
    for (; i < NN; i += gridDim.x * blockDim.x) g_deg[i] = 0;
}

__global__ void hist_kernel(const int* __restrict__ ei) {
    int i = blockIdx.x * blockDim.x + threadIdx.x;
    if (i < EE) atomicAdd(&g_deg[ei[EE + i]], 1);
}

__global__ void scan_kernel() {
    __shared__ int ssum[1024];
    const int T = 1024;
    int t = threadIdx.x;
    int chunk = (NN + T - 1) / T;
    int b = t * chunk;
    int e = b + chunk; if (e > NN) e = NN;
    int s = 0;
    for (int i = b; i < e; i++) s += g_deg[i];
    ssum[t] = s;
    __syncthreads();
    for (int off = 1; off < T; off <<= 1) {
        int v = (t >= off) ? ssum[t - off] : 0;
        __syncthreads();
        ssum[t] += v;
        __syncthreads();
    }
    int offset = (t == 0) ? 0 : ssum[t - 1];
    if (t == 0) g_rowptr[0] = 0;
    int run = offset;
    for (int i = b; i < e; i++) {
        g_cursor[i] = run;
        run += g_deg[i];
        g_rowptr[i + 1] = run;
    }
}

__global__ void scatter_kernel(const int* __restrict__ ei) {
    int i = blockIdx.x * blockDim.x + threadIdx.x;
    if (i < EE) {
        int d = ei[EE + i];
        int pos = atomicAdd(&g_cursor[d], 1);
        g_col[pos] = ei[i];
    }
}

__device__ __forceinline__ float lrelu(float x) { return x > 0.f ? x : NEG * x; }

// ---------------- GEMM1 (128x128x16, 8x8 microtile) + fused attention logits ----------------
__global__ void __launch_bounds__(256, 2)
gemm1_kernel(const float* __restrict__ A, const float* __restrict__ B,
             const float* __restrict__ attS, const float* __restrict__ attD) {
    __shared__ float As[16][128];
    __shared__ float Bs[16][128];
    int tid = threadIdx.x;
    int bm = blockIdx.x * 128;
    int bn = blockIdx.y * 128;
    int tx = tid & 15, ty = tid >> 4;

    // per-thread attention vector slice: cols bn + tx*8 .. +8 within one head
    int headLocal = tx >> 2;                 // 0..3
    int headGlobal = (bn >> 5) + headLocal;
    int cbase = (tx & 3) * 8;                // channel offset within head
    float aS[8], aD[8];
#pragma unroll
    for (int j = 0; j < 8; j++) {
        aS[j] = attS[headGlobal * HID + cbase + j];
        aD[j] = attD[headGlobal * HID + cbase + j];
    }

    float acc[8][8];
#pragma unroll
    for (int i = 0; i < 8; i++)
#pragma unroll
        for (int j = 0; j < 8; j++) acc[i][j] = 0.f;

    int arow = tid >> 2;                     // 0..63 (and +64)
    int acol = (tid & 3) << 2;               // 0,4,8,12
    int brow = tid >> 4;                     // 0..15
    int bcol = (tid & 15) << 3;              // 0..120

    for (int k0 = 0; k0 < INC; k0 += 16) {
        float4 a0 = make_float4(0.f,0.f,0.f,0.f), a1 = a0;
        if (bm + arow < NN)
            a0 = *(const float4*)(A + (size_t)(bm + arow) * INC + k0 + acol);
        if (bm + arow + 64 < NN)
            a1 = *(const float4*)(A + (size_t)(bm + arow + 64) * INC + k0 + acol);
        float4 b0 = *(const float4*)(B + (size_t)(k0 + brow) * C1 + bn + bcol);
        float4 b1 = *(const float4*)(B + (size_t)(k0 + brow) * C1 + bn + bcol + 4);
        __syncthreads();
        As[acol + 0][arow] = a0.x; As[acol + 1][arow] = a0.y;
        As[acol + 2][arow] = a0.z; As[acol + 3][arow] = a0.w;
        As[acol + 0][arow + 64] = a1.x; As[acol + 1][arow + 64] = a1.y;
        As[acol + 2][arow + 64] = a1.z; As[acol + 3][arow + 64] = a1.w;
        *(float4*)&Bs[brow][bcol]     = b0;
        *(float4*)&Bs[brow][bcol + 4] = b1;
        __syncthreads();
#pragma unroll
        for (int kk = 0; kk < 16; kk++) {
            float4 ra0 = *(float4*)&As[kk][ty * 8];
            float4 ra1 = *(float4*)&As[kk][ty * 8 + 4];
            float4 rb0 = *(float4*)&Bs[kk][tx * 8];
            float4 rb1 = *(float4*)&Bs[kk][tx * 8 + 4];
            float ar[8] = {ra0.x, ra0.y, ra0.z, ra0.w, ra1.x, ra1.y, ra1.z, ra1.w};
            float br[8] = {rb0.x, rb0.y, rb0.z, rb0.w, rb1.x, rb1.y, rb1.z, rb1.w};
#pragma unroll
            for (int i = 0; i < 8; i++)
#pragma unroll
                for (int j = 0; j < 8; j++) acc[i][j] += ar[i] * br[j];
        }
    }

    // write xl1 + per-thread partial logits
    float ps[8], pd[8];
#pragma unroll
    for (int i = 0; i < 8; i++) {
        int row = bm + ty * 8 + i;
        float s_acc = 0.f, d_acc = 0.f;
#pragma unroll
        for (int j = 0; j < 8; j++) { s_acc += acc[i][j] * aS[j]; d_acc += acc[i][j] * aD[j]; }
        ps[i] = s_acc; pd[i] = d_acc;
        if (row < NN) {
            float4 v0 = make_float4(acc[i][0], acc[i][1], acc[i][2], acc[i][3]);
            float4 v1 = make_float4(acc[i][4], acc[i][5], acc[i][6], acc[i][7]);
            float4* p = (float4*)(g_xl1 + (size_t)row * C1 + bn + tx * 8);
            p[0] = v0; p[1] = v1;
        }
    }

    // reduce logits across the 4 tx-slices of each head (reuse smem)
    float* sS = &As[0][0];     // 2048 floats = 128 rows x 16 tx
    float* sD = &Bs[0][0];
    __syncthreads();
#pragma unroll
    for (int i = 0; i < 8; i++) {
        sS[(ty * 8 + i) * 16 + tx] = ps[i];
        sD[(ty * 8 + i) * 16 + tx] = pd[i];
    }
    __syncthreads();
    // 512 (row, head) pairs; 256 threads handle 2 each
#pragma unroll
    for (int rep = 0; rep < 2; rep++) {
        int p = tid + rep * 256;
        int head = p & 3;
        int row = p >> 2;
        float s = sS[row * 16 + head * 4 + 0] + sS[row * 16 + head * 4 + 1]
                + sS[row * 16 + head * 4 + 2] + sS[row * 16 + head * 4 + 3];
        float d = sD[row * 16 + head * 4 + 0] + sD[row * 16 + head * 4 + 1]
                + sD[row * 16 + head * 4 + 2] + sD[row * 16 + head * 4 + 3];
        int rg = bm + row;
        if (rg < NN) {
            g_as1[rg * HEADS + (bn >> 5) + head] = s;
            g_ad1[rg * HEADS + (bn >> 5) + head] = d;
        }
    }
}

// ---------------- aggregation layer1: warp per dst node, 2 passes, no max ----------------
__global__ void agg1_kernel(const float* __restrict__ b1) {
    int warp = (blockIdx.x * blockDim.x + threadIdx.x) >> 5;
    if (warp >= NN) return;
    int lane = threadIdx.x & 31;
    int node = warp;
    int start = g_rowptr[node];
    int end   = g_rowptr[node + 1];

    float adst[HEADS], eself[HEADS];
    {
        const float4* dp = (const float4*)(g_ad1 + (size_t)node * HEADS);
        float4 d0 = dp[0], d1 = dp[1];
        const float4* sp = (const float4*)(g_as1 + (size_t)node * HEADS);
        float4 s0 = sp[0], s1 = sp[1];
        float dv[8] = {d0.x,d0.y,d0.z,d0.w,d1.x,d1.y,d1.z,d1.w};
        float sv[8] = {s0.x,s0.y,s0.z,s0.w,s1.x,s1.y,s1.z,s1.w};
#pragma unroll
        for (int h = 0; h < HEADS; h++) {
            adst[h] = dv[h];
            eself[h] = __expf(lrelu(sv[h] + dv[h]));
        }
    }

    // pass 1: compute exp per edge per head, store to g_e, accumulate denom
    float ssum[HEADS];
#pragma unroll
    for (int h = 0; h < HEADS; h++) ssum[h] = (lane == 0) ? eself[h] : 0.f;
    for (int idx = start + lane; idx < end; idx += 32) {
        int s = g_col[idx];
        const float4* ap = (const float4*)(g_as1 + (size_t)s * HEADS);
        float4 a0 = ap[0], a1 = ap[1];
        float av[8] = {a0.x,a0.y,a0.z,a0.w,a1.x,a1.y,a1.z,a1.w};
        float ev[8];
#pragma unroll
        for (int h = 0; h < HEADS; h++) {
            float e = __expf(lrelu(av[h] + adst[h]));
            ev[h] = e;
            ssum[h] += e;
        }
        float4* ep = (float4*)(g_e + (size_t)idx * HEADS);
        ep[0] = make_float4(ev[0], ev[1], ev[2], ev[3]);
        ep[1] = make_float4(ev[4], ev[5], ev[6], ev[7]);
    }
#pragma unroll
    for (int h = 0; h < HEADS; h++)
#pragma unroll
        for (int o = 16; o; o >>= 1) ssum[h] += __shfl_xor_sync(0xffffffffu, ssum[h], o);

    float inv[HEADS];
#pragma unroll
    for (int h = 0; h < HEADS; h++) inv[h] = 1.f / (ssum[h] + EPSV);

    int myh = lane >> 2;
    float invh = 0.f, aself = 0.f;
#pragma unroll
    for (int h = 0; h < HEADS; h++)
        if (h == myh) { invh = inv[h]; aself = eself[h] * inv[h]; }

    // pass 2: weighted feature aggregation. lane covers channels [lane*8, lane*8+8)
    int c0 = lane * 8;
    float acc[8];
    {
        const float4* xp = (const float4*)(g_xl1 + (size_t)node * C1 + c0);
        float4 v0 = xp[0], v1 = xp[1];
        acc[0] = aself*v0.x; acc[1] = aself*v0.y; acc[2] = aself*v0.z; acc[3] = aself*v0.w;
        acc[4] = aself*v1.x; acc[5] = aself*v1.y; acc[6] = aself*v1.z; acc[7] = aself*v1.w;
    }
    for (int idx = start; idx < end; idx++) {
        int s = g_col[idx];                     // broadcast
        float a = g_e[(size_t)idx * HEADS + myh] * invh;   // 32B sector broadcast
        const float4* xp = (const float4*)(g_xl1 + (size_t)s * C1 + c0);
        float4 v0 = xp[0], v1 = xp[1];
        acc[0] += a*v0.x; acc[1] += a*v0.y; acc[2] += a*v0.z; acc[3] += a*v0.w;
        acc[4] += a*v1.x; acc[5] += a*v1.y; acc[6] += a*v1.z; acc[7] += a*v1.w;
    }
    float ov[8];
#pragma unroll
    for (int j = 0; j < 8; j++) {
        float v = acc[j] + b1[c0 + j];
        ov[j] = v > 0.f ? v : (__expf(v) - 1.f);
    }
    float4* hp = (float4*)(g_h1 + (size_t)node * C1 + c0);
    hp[0] = make_float4(ov[0], ov[1], ov[2], ov[3]);
    hp[1] = make_float4(ov[4], ov[5], ov[6], ov[7]);
}

// ---------------- GEMM2 + logits2 ----------------
#define WST 260
__global__ void gemm2_kernel(const float* __restrict__ W2,
                             const float* __restrict__ att_s2,
                             const float* __restrict__ att_d2) {
    __shared__ float Wst[16 * WST];        // transposed, padded
    __shared__ float Hs[16 * 256];
    __shared__ float sa[16], sd[16];
    int tid = threadIdx.x;
    for (int i = tid; i < 4096; i += 256) {
        int k = i >> 4, c = i & 15;
        Wst[c * WST + k] = W2[i];
    }
    if (tid < 16) { sa[tid] = att_s2[tid]; sd[tid] = att_d2[tid]; }
    int base = blockIdx.x * 16;
    for (int i = tid; i < 4096; i += 256) {
        int r = i >> 8, k = i & 255;
        int row = base + r;
        Hs[i] = (row < NN) ? g_h1[(size_t)row * C1 + k] : 0.f;
    }
    __syncthreads();
    int r = tid >> 4, c = tid & 15;
    int row = base + r;
    float acc = 0.f;
#pragma unroll 8
    for (int k4 = 0; k4 < 64; k4++) {
        float4 h = *(float4*)&Hs[r * 256 + k4 * 4];
        float4 w = *(float4*)&Wst[c * WST + k4 * 4];
        acc += h.x*w.x + h.y*w.y + h.z*w.z + h.w*w.w;
    }
    if (row < NN) g_xl2[(size_t)row * OUTC + c] = acc;
    float vs = acc * sa[c];
    float vd = acc * sd[c];
#pragma unroll
    for (int o = 8; o; o >>= 1) {
        vs += __shfl_xor_sync(0xffffffffu, vs, o, 16);
        vd += __shfl_xor_sync(0xffffffffu, vd, o, 16);
    }
    if (c == 0 && row < NN) { g_as2[row] = vs; g_ad2[row] = vd; }
}

// ---------------- aggregation layer2 (no max, 2 passes) ----------------
__global__ void agg2_kernel(const float* __restrict__ b2, float* __restrict__ out) {
    int warp = (blockIdx.x * blockDim.x + threadIdx.x) >> 5;
    if (warp >= NN) return;
    int lane = threadIdx.x & 31;
    int node = warp;
    int start = g_rowptr[node];
    int end   = g_rowptr[node + 1];

    float adst = g_ad2[node];
    float es = __expf(lrelu(g_as2[node] + adst));
    float ss = (lane == 0) ? es : 0.f;
    for (int idx = start + lane; idx < end; idx += 32)
        ss += __expf(lrelu(g_as2[g_col[idx]] + adst));
#pragma unroll
    for (int o = 16; o; o >>= 1) ss += __shfl_xor_sync(0xffffffffu, ss, o);
    float inv = 1.f / (ss + EPSV);

    int c = lane & 15;
    int half = lane >> 4;
    float acc = 0.f;
    if (half == 0) acc = es * inv * g_xl2[(size_t)node * OUTC + c];
    for (int idx = start + half; idx < end; idx += 2) {
        int s = g_col[idx];
        float a = __expf(lrelu(g_as2[s] + adst)) * inv;
        acc += a * g_xl2[(size_t)s * OUTC + c];
    }
    acc += __shfl_down_sync(0xffffffffu, acc, 16);
    if (lane < 16) out[(size_t)node * OUTC + c] = acc + b2[c];
}

// ---------------- launch ----------------
extern "C" void kernel_launch(void* const* d_in, const int* in_sizes, int n_in,
                              void* d_out, int out_size) {
    const float* x     = (const float*)d_in[0];
    const int*   ei    = (const int*)d_in[1];
    const float* W1    = (const float*)d_in[2];
    const float* atts1 = (const float*)d_in[3];
    const float* attd1 = (const float*)d_in[4];
    const float* b1    = (const float*)d_in[5];
    const float* W2    = (const float*)d_in[6];
    const float* atts2 = (const float*)d_in[7];
    const float* attd2 = (const float*)d_in[8];
    const float* b2    = (const float*)d_in[9];
    float* out = (float*)d_out;

    zero_deg_kernel<<<64, 256>>>();
    hist_kernel<<<(EE + 255) / 256, 256>>>(ei);
    scan_kernel<<<1, 1024>>>();
    scatter_kernel<<<(EE + 255) / 256, 256>>>(ei);

    gemm1_kernel<<<dim3((NN + 127) / 128, 2), 256>>>(x, W1, atts1, attd1);
    agg1_kernel<<<(NN + 7) / 8, 256>>>(b1);
    gemm2_kernel<<<(NN + 15) / 16, 256>>>(W2, atts2, attd2);
    agg2_kernel<<<(NN + 7) / 8, 256>>>(b2, out);
}

// round 5
// speedup vs baseline: 1.1085x; 1.0130x over previous
#include <cuda_runtime.h>
#include <cuda_bf16.h>

// Problem constants
#define NN    50000
#define EE    800000
#define INC   128
#define HEADS 8
#define HID   32
#define C1    256
#define OUTC  16
#define NEG   0.2f
#define EPSV  1e-16f

// ---------------- scratch ----------------
__device__ float g_xl1[NN * C1];
__device__ float g_h1 [NN * C1];
__device__ float g_as1[NN * HEADS];
__device__ float g_ad1[NN * HEADS];
__device__ float g_e  [EE * HEADS];
__device__ float g_xl2[NN * OUTC];
__device__ float g_as2[NN];
__device__ float g_ad2[NN];
__device__ int   g_deg[NN];
__device__ int   g_rowptr[NN + 1];
__device__ int   g_cursor[NN];
__device__ int   g_col[EE];
__device__ __nv_bfloat16 g_a1 [NN * 512];    // [Xh|Xl|Xh|Xl] per row
__device__ __nv_bfloat16 g_w1t[C1 * 512];    // transposed: [n][Wh|Wh|Wl|Wl]

// ---------------- CSR build ----------------
__global__ void zero_deg_kernel() {
    int i = blockIdx.x * blockDim.x + threadIdx.x;
    for (; i < NN; i += gridDim.x * blockDim.x) g_deg[i] = 0;
}

__global__ void hist_kernel(const int* __restrict__ ei) {
    int i = blockIdx.x * blockDim.x + threadIdx.x;
    if (i < EE) atomicAdd(&g_deg[ei[EE + i]], 1);
}

__global__ void scan_kernel() {
    __shared__ int ssum[1024];
    const int T = 1024;
    int t = threadIdx.x;
    int chunk = (NN + T - 1) / T;
    int b = t * chunk;
    int e = b + chunk; if (e > NN) e = NN;
    int s = 0;
    for (int i = b; i < e; i++) s += g_deg[i];
    ssum[t] = s;
    __syncthreads();
    for (int off = 1; off < T; off <<= 1) {
        int v = (t >= off) ? ssum[t - off] : 0;
        __syncthreads();
        ssum[t] += v;
        __syncthreads();
    }
    int offset = (t == 0) ? 0 : ssum[t - 1];
    if (t == 0) g_rowptr[0] = 0;
    int run = offset;
    for (int i = b; i < e; i++) {
        g_cursor[i] = run;
        run += g_deg[i];
        g_rowptr[i + 1] = run;
    }
}

__global__ void scatter_kernel(const int* __restrict__ ei) {
    int i = blockIdx.x * blockDim.x + threadIdx.x;
    if (i < EE) {
        int d = ei[EE + i];
        int pos = atomicAdd(&g_cursor[d], 1);
        g_col[pos] = ei[i];
    }
}

__device__ __forceinline__ float lrelu(float x) { return x > 0.f ? x : NEG * x; }

// ---------------- bf16 split prep ----------------
__global__ void prep_x_kernel(const float* __restrict__ x) {
    int i = blockIdx.x * blockDim.x + threadIdx.x;
    if (i >= NN * INC) return;
    int n = i >> 7, k = i & 127;
    float v = x[i];
    __nv_bfloat16 hi = __float2bfloat16(v);
    __nv_bfloat16 lo = __float2bfloat16(v - __bfloat162float(hi));
    __nv_bfloat16* p = g_a1 + (size_t)n * 512 + k;
    p[0]   = hi;
    p[128] = lo;
    p[256] = hi;
    p[384] = lo;
}

__global__ void prep_w_kernel(const float* __restrict__ W1) {
    int i = blockIdx.x * blockDim.x + threadIdx.x;  // 128*256
    if (i >= INC * C1) return;
    int k = i >> 8, n = i & 255;
    float v = W1[i];                         // W1[k][n]
    __nv_bfloat16 hi = __float2bfloat16(v);
    __nv_bfloat16 lo = __float2bfloat16(v - __bfloat162float(hi));
    __nv_bfloat16* p = g_w1t + (size_t)n * 512 + k;
    p[0]   = hi;
    p[128] = hi;
    p[256] = lo;
    p[384] = lo;
}

// ---------------- HMMA helper ----------------
__device__ __forceinline__ void mma_bf16(float* d, const unsigned* a, const unsigned* b) {
    asm volatile(
        "mma.sync.aligned.m16n8k16.row.col.f32.bf16.bf16.f32 "
        "{%0,%1,%2,%3}, {%4,%5,%6,%7}, {%8,%9}, {%0,%1,%2,%3};\n"
        : "+f"(d[0]), "+f"(d[1]), "+f"(d[2]), "+f"(d[3])
        : "r"(a[0]), "r"(a[1]), "r"(a[2]), "r"(a[3]), "r"(b[0]), "r"(b[1]));
}

// ---------------- GEMM1 via tensor cores + fused attention logits ----------------
// A' [NN,512] bf16, B' (g_w1t) [256,512] bf16 N-major. D = A'.B'^T = x@W1 (split-exact).
// Block: 256 thr = 8 warps (4 M x 2 N). BM=128, BN=64. Warp tile 32x32.
#define AST 72
__global__ void __launch_bounds__(256, 2)
gemm1_mma_kernel(const float* __restrict__ attS, const float* __restrict__ attD) {
    __shared__ __nv_bfloat16 As[128 * AST];
    __shared__ __nv_bfloat16 Bs[64 * AST];
    int tid = threadIdx.x;
    int warp = tid >> 5, lane = tid & 31;
    int wm = warp >> 1, wn = warp & 1;
    int bm = blockIdx.x * 128, bn = blockIdx.y * 64;
    int r = lane >> 2, c = lane & 3;
    int head = (bn + wn * 32) >> 5;

    float aSv[8], aDv[8];
#pragma unroll
    for (int n = 0; n < 4; n++) {
        aSv[n * 2]     = attS[head * HID + n * 8 + 2 * c];
        aSv[n * 2 + 1] = attS[head * HID + n * 8 + 2 * c + 1];
        aDv[n * 2]     = attD[head * HID + n * 8 + 2 * c];
        aDv[n * 2 + 1] = attD[head * HID + n * 8 + 2 * c + 1];
    }

    float acc[2][4][4];
#pragma unroll
    for (int m = 0; m < 2; m++)
#pragma unroll
        for (int n = 0; n < 4; n++)
#pragma unroll
            for (int j = 0; j < 4; j++) acc[m][n][j] = 0.f;

    for (int k0 = 0; k0 < 512; k0 += 64) {
#pragma unroll
        for (int it = 0; it < 4; it++) {
            int idx = it * 256 + tid;
            int row = idx >> 3, c8 = (idx & 7) << 3;
            uint4 v = make_uint4(0u, 0u, 0u, 0u);
            if (bm + row < NN)
                v = *(const uint4*)(g_a1 + (size_t)(bm + row) * 512 + k0 + c8);
            *(uint4*)&As[row * AST + c8] = v;
        }
#pragma unroll
        for (int it = 0; it < 2; it++) {
            int idx = it * 256 + tid;
            int n = idx >> 3, c8 = (idx & 7) << 3;
            *(uint4*)&Bs[n * AST + c8] =
                *(const uint4*)(g_w1t + (size_t)(bn + n) * 512 + k0 + c8);
        }
        __syncthreads();
#pragma unroll
        for (int kk = 0; kk < 64; kk += 16) {
            unsigned af[2][4], bf[4][2];
#pragma unroll
            for (int m = 0; m < 2; m++) {
                int row = wm * 32 + m * 16 + r;
                af[m][0] = *(unsigned*)&As[row * AST + kk + 2 * c];
                af[m][1] = *(unsigned*)&As[(row + 8) * AST + kk + 2 * c];
                af[m][2] = *(unsigned*)&As[row * AST + kk + 2 * c + 8];
                af[m][3] = *(unsigned*)&As[(row + 8) * AST + kk + 2 * c + 8];
            }
#pragma unroll
            for (int n = 0; n < 4; n++) {
                int col = wn * 32 + n * 8 + r;
                bf[n][0] = *(unsigned*)&Bs[col * AST + kk + 2 * c];
                bf[n][1] = *(unsigned*)&Bs[col * AST + kk + 2 * c + 8];
            }
#pragma unroll
            for (int m = 0; m < 2; m++)
#pragma unroll
                for (int n = 0; n < 4; n++) mma_bf16(acc[m][n], af[m], bf[n]);
        }
        __syncthreads();
    }

    // epilogue: xl1 stores + fused attention logits
#pragma unroll
    for (int m = 0; m < 2; m++) {
        int row0 = bm + wm * 32 + m * 16 + r;
#pragma unroll
        for (int n = 0; n < 4; n++) {
            int col = bn + wn * 32 + n * 8 + 2 * c;
            if (row0 < NN)
                *(float2*)(g_xl1 + (size_t)row0 * C1 + col) = make_float2(acc[m][n][0], acc[m][n][1]);
            if (row0 + 8 < NN)
                *(float2*)(g_xl1 + (size_t)(row0 + 8) * C1 + col) = make_float2(acc[m][n][2], acc[m][n][3]);
        }
        float s0 = 0.f, s1 = 0.f, d0 = 0.f, d1 = 0.f;
#pragma unroll
        for (int n = 0; n < 4; n++) {
            s0 += acc[m][n][0] * aSv[n * 2] + acc[m][n][1] * aSv[n * 2 + 1];
            s1 += acc[m][n][2] * aSv[n * 2] + acc[m][n][3] * aSv[n * 2 + 1];
            d0 += acc[m][n][0] * aDv[n * 2] + acc[m][n][1] * aDv[n * 2 + 1];
            d1 += acc[m][n][2] * aDv[n * 2] + acc[m][n][3] * aDv[n * 2 + 1];
        }
#pragma unroll
        for (int o = 1; o <= 2; o <<= 1) {
            s0 += __shfl_xor_sync(0xffffffffu, s0, o);
            s1 += __shfl_xor_sync(0xffffffffu, s1, o);
            d0 += __shfl_xor_sync(0xffffffffu, d0, o);
            d1 += __shfl_xor_sync(0xffffffffu, d1, o);
        }
        if (c == 0) {
            if (row0 < NN)     { g_as1[row0 * HEADS + head] = s0;       g_ad1[row0 * HEADS + head] = d0; }
            if (row0 + 8 < NN) { g_as1[(row0 + 8) * HEADS + head] = s1; g_ad1[(row0 + 8) * HEADS + head] = d1; }
        }
    }
}

// ---------------- aggregation layer1: warp per dst node, 2 passes, no max ----------------
__global__ void agg1_kernel(const float* __restrict__ b1) {
    int warp = (blockIdx.x * blockDim.x + threadIdx.x) >> 5;
    if (warp >= NN) return;
    int lane = threadIdx.x & 31;
    int node = warp;
    int start = g_rowptr[node];
    int end   = g_rowptr[node + 1];

    float adst[HEADS], eself[HEADS];
    {
        const float4* dp = (const float4*)(g_ad1 + (size_t)node * HEADS);
        float4 d0 = dp[0], d1 = dp[1];
        const float4* sp = (const float4*)(g_as1 + (size_t)node * HEADS);
        float4 s0 = sp[0], s1 = sp[1];
        float dv[8] = {d0.x,d0.y,d0.z,d0.w,d1.x,d1.y,d1.z,d1.w};
        float sv[8] = {s0.x,s0.y,s0.z,s0.w,s1.x,s1.y,s1.z,s1.w};
#pragma unroll
        for (int h = 0; h < HEADS; h++) {
            adst[h] = dv[h];
            eself[h] = __expf(lrelu(sv[h] + dv[h]));
        }
    }

    float ssum[HEADS];
#pragma unroll
    for (int h = 0; h < HEADS; h++) ssum[h] = (lane == 0) ? eself[h] : 0.f;
    for (int idx = start + lane; idx < end; idx += 32) {
        int s = g_col[idx];
        const float4* ap = (const float4*)(g_as1 + (size_t)s * HEADS);
        float4 a0 = ap[0], a1 = ap[1];
        float av[8] = {a0.x,a0.y,a0.z,a0.w,a1.x,a1.y,a1.z,a1.w};
        float ev[8];
#pragma unroll
        for (int h = 0; h < HEADS; h++) {
            float e = __expf(lrelu(av[h] + adst[h]));
            ev[h] = e;
            ssum[h] += e;
        }
        float4* ep = (float4*)(g_e + (size_t)idx * HEADS);
        ep[0] = make_float4(ev[0], ev[1], ev[2], ev[3]);
        ep[1] = make_float4(ev[4], ev[5], ev[6], ev[7]);
    }
#pragma unroll
    for (int h = 0; h < HEADS; h++)
#pragma unroll
        for (int o = 16; o; o >>= 1) ssum[h] += __shfl_xor_sync(0xffffffffu, ssum[h], o);

    float inv[HEADS];
#pragma unroll
    for (int h = 0; h < HEADS; h++) inv[h] = 1.f / (ssum[h] + EPSV);

    int myh = lane >> 2;
    float invh = 0.f, aself = 0.f;
#pragma unroll
    for (int h = 0; h < HEADS; h++)
        if (h == myh) { invh = inv[h]; aself = eself[h] * inv[h]; }

    int c0 = lane * 8;
    float acc[8];
    {
        const float4* xp = (const float4*)(g_xl1 + (size_t)node * C1 + c0);
        float4 v0 = xp[0], v1 = xp[1];
        acc[0] = aself*v0.x; acc[1] = aself*v0.y; acc[2] = aself*v0.z; acc[3] = aself*v0.w;
        acc[4] = aself*v1.x; acc[5] = aself*v1.y; acc[6] = aself*v1.z; acc[7] = aself*v1.w;
    }
#pragma unroll 2
    for (int idx = start; idx < end; idx++) {
        int s = g_col[idx];
        float a = g_e[(size_t)idx * HEADS + myh] * invh;
        const float4* xp = (const float4*)(g_xl1 + (size_t)s * C1 + c0);
        float4 v0 = xp[0], v1 = xp[1];
        acc[0] += a*v0.x; acc[1] += a*v0.y; acc[2] += a*v0.z; acc[3] += a*v0.w;
        acc[4] += a*v1.x; acc[5] += a*v1.y; acc[6] += a*v1.z; acc[7] += a*v1.w;
    }
    float ov[8];
#pragma unroll
    for (int j = 0; j < 8; j++) {
        float v = acc[j] + b1[c0 + j];
        ov[j] = v > 0.f ? v : (__expf(v) - 1.f);
    }
    float4* hp = (float4*)(g_h1 + (size_t)node * C1 + c0);
    hp[0] = make_float4(ov[0], ov[1], ov[2], ov[3]);
    hp[1] = make_float4(ov[4], ov[5], ov[6], ov[7]);
}

// ---------------- GEMM2 + logits2 ----------------
#define WST 260
__global__ void gemm2_kernel(const float* __restrict__ W2,
                             const float* __restrict__ att_s2,
                             const float* __restrict__ att_d2) {
    __shared__ float Wst[16 * WST];
    __shared__ float Hs[16 * 256];
    __shared__ float sa[16], sd[16];
    int tid = threadIdx.x;
    for (int i = tid; i < 4096; i += 256) {
        int k = i >> 4, c = i & 15;
        Wst[c * WST + k] = W2[i];
    }
    if (tid < 16) { sa[tid] = att_s2[tid]; sd[tid] = att_d2[tid]; }
    int base = blockIdx.x * 16;
    for (int i = tid; i < 4096; i += 256) {
        int r = i >> 8, k = i & 255;
        int row = base + r;
        Hs[i] = (row < NN) ? g_h1[(size_t)row * C1 + k] : 0.f;
    }
    __syncthreads();
    int r = tid >> 4, c = tid & 15;
    int row = base + r;
    float acc = 0.f;
#pragma unroll 8
    for (int k4 = 0; k4 < 64; k4++) {
        float4 h = *(float4*)&Hs[r * 256 + k4 * 4];
        float4 w = *(float4*)&Wst[c * WST + k4 * 4];
        acc += h.x*w.x + h.y*w.y + h.z*w.z + h.w*w.w;
    }
    if (row < NN) g_xl2[(size_t)row * OUTC + c] = acc;
    float vs = acc * sa[c];
    float vd = acc * sd[c];
#pragma unroll
    for (int o = 8; o; o >>= 1) {
        vs += __shfl_xor_sync(0xffffffffu, vs, o, 16);
        vd += __shfl_xor_sync(0xffffffffu, vd, o, 16);
    }
    if (c == 0 && row < NN) { g_as2[row] = vs; g_ad2[row] = vd; }
}

// ---------------- aggregation layer2 ----------------
__global__ void agg2_kernel(const float* __restrict__ b2, float* __restrict__ out) {
    int warp = (blockIdx.x * blockDim.x + threadIdx.x) >> 5;
    if (warp >= NN) return;
    int lane = threadIdx.x & 31;
    int node = warp;
    int start = g_rowptr[node];
    int end   = g_rowptr[node + 1];

    float adst = g_ad2[node];
    float es = __expf(lrelu(g_as2[node] + adst));
    float ss = (lane == 0) ? es : 0.f;
    for (int idx = start + lane; idx < end; idx += 32)
        ss += __expf(lrelu(g_as2[g_col[idx]] + adst));
#pragma unroll
    for (int o = 16; o; o >>= 1) ss += __shfl_xor_sync(0xffffffffu, ss, o);
    float inv = 1.f / (ss + EPSV);

    int c = lane & 15;
    int half = lane >> 4;
    float acc = 0.f;
    if (half == 0) acc = es * inv * g_xl2[(size_t)node * OUTC + c];
    for (int idx = start + half; idx < end; idx += 2) {
        int s = g_col[idx];
        float a = __expf(lrelu(g_as2[s] + adst)) * inv;
        acc += a * g_xl2[(size_t)s * OUTC + c];
    }
    acc += __shfl_down_sync(0xffffffffu, acc, 16);
    if (lane < 16) out[(size_t)node * OUTC + c] = acc + b2[c];
}

// ---------------- launch ----------------
extern "C" void kernel_launch(void* const* d_in, const int* in_sizes, int n_in,
                              void* d_out, int out_size) {
    const float* x     = (const float*)d_in[0];
    const int*   ei    = (const int*)d_in[1];
    const float* W1    = (const float*)d_in[2];
    const float* atts1 = (const float*)d_in[3];
    const float* attd1 = (const float*)d_in[4];
    const float* b1    = (const float*)d_in[5];
    const float* W2    = (const float*)d_in[6];
    const float* atts2 = (const float*)d_in[7];
    const float* attd2 = (const float*)d_in[8];
    const float* b2    = (const float*)d_in[9];
    float* out = (float*)d_out;

    zero_deg_kernel<<<64, 256>>>();
    hist_kernel<<<(EE + 255) / 256, 256>>>(ei);
    prep_x_kernel<<<(NN * INC + 255) / 256, 256>>>(x);
    prep_w_kernel<<<(INC * C1 + 255) / 256, 256>>>(W1);
    scan_kernel<<<1, 1024>>>();
    scatter_kernel<<<(EE + 255) / 256, 256>>>(ei);

    gemm1_mma_kernel<<<dim3((NN + 127) / 128, 4), 256>>>(atts1, attd1);
    agg1_kernel<<<(NN + 7) / 8, 256>>>(b1);
    gemm2_kernel<<<(NN + 15) / 16, 256>>>(W2, atts2, attd2);
    agg2_kernel<<<(NN + 7) / 8, 256>>>(b2, out);
}

// round 6
// speedup vs baseline: 1.1803x; 1.0647x over previous
#include <cuda_runtime.h>
#include <cuda_bf16.h>

// Problem constants
#define NN    50000
#define EE    800000
#define INC   128
#define HEADS 8
#define HID   32
#define C1    256
#define OUTC  16
#define NEG   0.2f
#define EPSV  1e-16f

// ---------------- scratch ----------------
__device__ float g_xl1[NN * C1];
__device__ float g_h1 [NN * C1];
__device__ float g_as1[NN * HEADS];
__device__ float g_ad1[NN * HEADS];
__device__ float g_xl2[NN * OUTC];
__device__ float g_as2[NN];
__device__ float g_ad2[NN];
__device__ int   g_deg[NN];
__device__ int   g_rowptr[NN + 1];
__device__ int   g_cursor[NN];
__device__ int   g_col[EE];
__device__ __nv_bfloat16 g_a1 [NN * 512];    // [Xh|Xl|Xh|Xl] per row
__device__ __nv_bfloat16 g_w1t[C1 * 512];    // transposed: [n][Wh|Wh|Wl|Wl]

// ---------------- CSR build ----------------
__global__ void zero_deg_kernel() {
    int i = blockIdx.x * blockDim.x + threadIdx.x;
    for (; i < NN; i += gridDim.x * blockDim.x) g_deg[i] = 0;
}

__global__ void hist_kernel(const int* __restrict__ ei) {
    int i = blockIdx.x * blockDim.x + threadIdx.x;
    if (i < EE) atomicAdd(&g_deg[ei[EE + i]], 1);
}

__global__ void scan_kernel() {
    __shared__ int ssum[1024];
    const int T = 1024;
    int t = threadIdx.x;
    int chunk = (NN + T - 1) / T;
    int b = t * chunk;
    int e = b + chunk; if (e > NN) e = NN;
    int s = 0;
    for (int i = b; i < e; i++) s += g_deg[i];
    ssum[t] = s;
    __syncthreads();
    for (int off = 1; off < T; off <<= 1) {
        int v = (t >= off) ? ssum[t - off] : 0;
        __syncthreads();
        ssum[t] += v;
        __syncthreads();
    }
    int offset = (t == 0) ? 0 : ssum[t - 1];
    if (t == 0) g_rowptr[0] = 0;
    int run = offset;
    for (int i = b; i < e; i++) {
        g_cursor[i] = run;
        run += g_deg[i];
        g_rowptr[i + 1] = run;
    }
}

__global__ void scatter_kernel(const int* __restrict__ ei) {
    int i = blockIdx.x * blockDim.x + threadIdx.x;
    if (i < EE) {
        int d = ei[EE + i];
        int pos = atomicAdd(&g_cursor[d], 1);
        g_col[pos] = ei[i];
    }
}

__device__ __forceinline__ float lrelu(float x) { return x > 0.f ? x : NEG * x; }

// ---------------- bf16 split prep ----------------
__global__ void prep_x_kernel(const float* __restrict__ x) {
    int i = blockIdx.x * blockDim.x + threadIdx.x;
    if (i >= NN * INC) return;
    int n = i >> 7, k = i & 127;
    float v = x[i];
    __nv_bfloat16 hi = __float2bfloat16(v);
    __nv_bfloat16 lo = __float2bfloat16(v - __bfloat162float(hi));
    __nv_bfloat16* p = g_a1 + (size_t)n * 512 + k;
    p[0]   = hi;
    p[128] = lo;
    p[256] = hi;
    p[384] = lo;
}

__global__ void prep_w_kernel(const float* __restrict__ W1) {
    int i = blockIdx.x * blockDim.x + threadIdx.x;  // 128*256
    if (i >= INC * C1) return;
    int k = i >> 8, n = i & 255;
    float v = W1[i];                         // W1[k][n]
    __nv_bfloat16 hi = __float2bfloat16(v);
    __nv_bfloat16 lo = __float2bfloat16(v - __bfloat162float(hi));
    __nv_bfloat16* p = g_w1t + (size_t)n * 512 + k;
    p[0]   = hi;
    p[128] = hi;
    p[256] = lo;
    p[384] = lo;
}

// ---------------- HMMA helper ----------------
__device__ __forceinline__ void mma_bf16(float* d, const unsigned* a, const unsigned* b) {
    asm volatile(
        "mma.sync.aligned.m16n8k16.row.col.f32.bf16.bf16.f32 "
        "{%0,%1,%2,%3}, {%4,%5,%6,%7}, {%8,%9}, {%0,%1,%2,%3};\n"
        : "+f"(d[0]), "+f"(d[1]), "+f"(d[2]), "+f"(d[3])
        : "r"(a[0]), "r"(a[1]), "r"(a[2]), "r"(a[3]), "r"(b[0]), "r"(b[1]));
}

// ---------------- GEMM1 via tensor cores + fused attention logits ----------------
#define AST 72
__global__ void __launch_bounds__(256, 2)
gemm1_mma_kernel(const float* __restrict__ attS, const float* __restrict__ attD) {
    __shared__ __nv_bfloat16 As[128 * AST];
    __shared__ __nv_bfloat16 Bs[64 * AST];
    int tid = threadIdx.x;
    int warp = tid >> 5, lane = tid & 31;
    int wm = warp >> 1, wn = warp & 1;
    int bm = blockIdx.x * 128, bn = blockIdx.y * 64;
    int r = lane >> 2, c = lane & 3;
    int head = (bn + wn * 32) >> 5;

    float aSv[8], aDv[8];
#pragma unroll
    for (int n = 0; n < 4; n++) {
        aSv[n * 2]     = attS[head * HID + n * 8 + 2 * c];
        aSv[n * 2 + 1] = attS[head * HID + n * 8 + 2 * c + 1];
        aDv[n * 2]     = attD[head * HID + n * 8 + 2 * c];
        aDv[n * 2 + 1] = attD[head * HID + n * 8 + 2 * c + 1];
    }

    float acc[2][4][4];
#pragma unroll
    for (int m = 0; m < 2; m++)
#pragma unroll
        for (int n = 0; n < 4; n++)
#pragma unroll
            for (int j = 0; j < 4; j++) acc[m][n][j] = 0.f;

    for (int k0 = 0; k0 < 512; k0 += 64) {
#pragma unroll
        for (int it = 0; it < 4; it++) {
            int idx = it * 256 + tid;
            int row = idx >> 3, c8 = (idx & 7) << 3;
            uint4 v = make_uint4(0u, 0u, 0u, 0u);
            if (bm + row < NN)
                v = *(const uint4*)(g_a1 + (size_t)(bm + row) * 512 + k0 + c8);
            *(uint4*)&As[row * AST + c8] = v;
        }
#pragma unroll
        for (int it = 0; it < 2; it++) {
            int idx = it * 256 + tid;
            int n = idx >> 3, c8 = (idx & 7) << 3;
            *(uint4*)&Bs[n * AST + c8] =
                *(const uint4*)(g_w1t + (size_t)(bn + n) * 512 + k0 + c8);
        }
        __syncthreads();
#pragma unroll
        for (int kk = 0; kk < 64; kk += 16) {
            unsigned af[2][4], bf[4][2];
#pragma unroll
            for (int m = 0; m < 2; m++) {
                int row = wm * 32 + m * 16 + r;
                af[m][0] = *(unsigned*)&As[row * AST + kk + 2 * c];
                af[m][1] = *(unsigned*)&As[(row + 8) * AST + kk + 2 * c];
                af[m][2] = *(unsigned*)&As[row * AST + kk + 2 * c + 8];
                af[m][3] = *(unsigned*)&As[(row + 8) * AST + kk + 2 * c + 8];
            }
#pragma unroll
            for (int n = 0; n < 4; n++) {
                int col = wn * 32 + n * 8 + r;
                bf[n][0] = *(unsigned*)&Bs[col * AST + kk + 2 * c];
                bf[n][1] = *(unsigned*)&Bs[col * AST + kk + 2 * c + 8];
            }
#pragma unroll
            for (int m = 0; m < 2; m++)
#pragma unroll
                for (int n = 0; n < 4; n++) mma_bf16(acc[m][n], af[m], bf[n]);
        }
        __syncthreads();
    }

    // epilogue: xl1 stores + fused attention logits
#pragma unroll
    for (int m = 0; m < 2; m++) {
        int row0 = bm + wm * 32 + m * 16 + r;
#pragma unroll
        for (int n = 0; n < 4; n++) {
            int col = bn + wn * 32 + n * 8 + 2 * c;
            if (row0 < NN)
                *(float2*)(g_xl1 + (size_t)row0 * C1 + col) = make_float2(acc[m][n][0], acc[m][n][1]);
            if (row0 + 8 < NN)
                *(float2*)(g_xl1 + (size_t)(row0 + 8) * C1 + col) = make_float2(acc[m][n][2], acc[m][n][3]);
        }
        float s0 = 0.f, s1 = 0.f, d0 = 0.f, d1 = 0.f;
#pragma unroll
        for (int n = 0; n < 4; n++) {
            s0 += acc[m][n][0] * aSv[n * 2] + acc[m][n][1] * aSv[n * 2 + 1];
            s1 += acc[m][n][2] * aSv[n * 2] + acc[m][n][3] * aSv[n * 2 + 1];
            d0 += acc[m][n][0] * aDv[n * 2] + acc[m][n][1] * aDv[n * 2 + 1];
            d1 += acc[m][n][2] * aDv[n * 2] + acc[m][n][3] * aDv[n * 2 + 1];
        }
#pragma unroll
        for (int o = 1; o <= 2; o <<= 1) {
            s0 += __shfl_xor_sync(0xffffffffu, s0, o);
            s1 += __shfl_xor_sync(0xffffffffu, s1, o);
            d0 += __shfl_xor_sync(0xffffffffu, d0, o);
            d1 += __shfl_xor_sync(0xffffffffu, d1, o);
        }
        if (c == 0) {
            if (row0 < NN)     { g_as1[row0 * HEADS + head] = s0;       g_ad1[row0 * HEADS + head] = d0; }
            if (row0 + 8 < NN) { g_as1[(row0 + 8) * HEADS + head] = s1; g_ad1[(row0 + 8) * HEADS + head] = d1; }
        }
    }
}

// ---------------- aggregation layer1: warp per node, SINGLE PASS ----------------
// out = (sum_i e_i * x_i) / (sum_i e_i + eps); normalize at the end.
// Lane l covers channels [l*8, l*8+8) => head = l>>2. Each lane walks all edges.
__global__ void __launch_bounds__(256)
agg1_kernel(const float* __restrict__ b1) {
    int warp = (blockIdx.x * blockDim.x + threadIdx.x) >> 5;
    if (warp >= NN) return;
    int lane = threadIdx.x & 31;
    int node = warp;
    int start = g_rowptr[node];
    int end   = g_rowptr[node + 1];
    int myh = lane >> 2;
    int c0 = lane * 8;

    float ad = g_ad1[(size_t)node * HEADS + myh];
    float es = __expf(lrelu(g_as1[(size_t)node * HEADS + myh] + ad));

    float acc[8];
    float ssum = es;
    {
        const float4* xp = (const float4*)(g_xl1 + (size_t)node * C1 + c0);
        float4 v0 = xp[0], v1 = xp[1];
        acc[0] = es*v0.x; acc[1] = es*v0.y; acc[2] = es*v0.z; acc[3] = es*v0.w;
        acc[4] = es*v1.x; acc[5] = es*v1.y; acc[6] = es*v1.z; acc[7] = es*v1.w;
    }
#pragma unroll 4
    for (int idx = start; idx < end; idx++) {
        int s = g_col[idx];                                        // broadcast
        float e = __expf(lrelu(g_as1[(size_t)s * HEADS + myh] + ad));
        const float4* xp = (const float4*)(g_xl1 + (size_t)s * C1 + c0);
        float4 v0 = xp[0], v1 = xp[1];
        acc[0] += e*v0.x; acc[1] += e*v0.y; acc[2] += e*v0.z; acc[3] += e*v0.w;
        acc[4] += e*v1.x; acc[5] += e*v1.y; acc[6] += e*v1.z; acc[7] += e*v1.w;
        ssum += e;
    }
    float inv = 1.f / (ssum + EPSV);
    float ov[8];
#pragma unroll
    for (int j = 0; j < 8; j++) {
        float v = acc[j] * inv + b1[c0 + j];
        ov[j] = v > 0.f ? v : (__expf(v) - 1.f);
    }
    float4* hp = (float4*)(g_h1 + (size_t)node * C1 + c0);
    hp[0] = make_float4(ov[0], ov[1], ov[2], ov[3]);
    hp[1] = make_float4(ov[4], ov[5], ov[6], ov[7]);
}

// ---------------- GEMM2 + logits2 ----------------
#define WST 260
__global__ void gemm2_kernel(const float* __restrict__ W2,
                             const float* __restrict__ att_s2,
                             const float* __restrict__ att_d2) {
    __shared__ float Wst[16 * WST];
    __shared__ float Hs[16 * 256];
    __shared__ float sa[16], sd[16];
    int tid = threadIdx.x;
    for (int i = tid; i < 4096; i += 256) {
        int k = i >> 4, c = i & 15;
        Wst[c * WST + k] = W2[i];
    }
    if (tid < 16) { sa[tid] = att_s2[tid]; sd[tid] = att_d2[tid]; }
    int base = blockIdx.x * 16;
    for (int i = tid; i < 4096; i += 256) {
        int r = i >> 8, k = i & 255;
        int row = base + r;
        Hs[i] = (row < NN) ? g_h1[(size_t)row * C1 + k] : 0.f;
    }
    __syncthreads();
    int r = tid >> 4, c = tid & 15;
    int row = base + r;
    float acc = 0.f;
#pragma unroll 8
    for (int k4 = 0; k4 < 64; k4++) {
        float4 h = *(float4*)&Hs[r * 256 + k4 * 4];
        float4 w = *(float4*)&Wst[c * WST + k4 * 4];
        acc += h.x*w.x + h.y*w.y + h.z*w.z + h.w*w.w;
    }
    if (row < NN) g_xl2[(size_t)row * OUTC + c] = acc;
    float vs = acc * sa[c];
    float vd = acc * sd[c];
#pragma unroll
    for (int o = 8; o; o >>= 1) {
        vs += __shfl_xor_sync(0xffffffffu, vs, o, 16);
        vd += __shfl_xor_sync(0xffffffffu, vd, o, 16);
    }
    if (c == 0 && row < NN) { g_as2[row] = vs; g_ad2[row] = vd; }
}

// ---------------- aggregation layer2: SINGLE PASS ----------------
__global__ void __launch_bounds__(256)
agg2_kernel(const float* __restrict__ b2, float* __restrict__ out) {
    int warp = (blockIdx.x * blockDim.x + threadIdx.x) >> 5;
    if (warp >= NN) return;
    int lane = threadIdx.x & 31;
    int node = warp;
    int start = g_rowptr[node];
    int end   = g_rowptr[node + 1];

    float ad = g_ad2[node];
    int c = lane & 15;
    int half = lane >> 4;

    float acc = 0.f, ssum = 0.f;
    if (half == 0) {
        float es = __expf(lrelu(g_as2[node] + ad));
        acc = es * g_xl2[(size_t)node * OUTC + c];
        ssum = es;
    }
#pragma unroll 4
    for (int idx = start + half; idx < end; idx += 2) {
        int s = g_col[idx];
        float e = __expf(lrelu(g_as2[s] + ad));
        acc += e * g_xl2[(size_t)s * OUTC + c];
        ssum += e;
    }
    acc  += __shfl_down_sync(0xffffffffu, acc, 16);
    ssum += __shfl_down_sync(0xffffffffu, ssum, 16);
    if (lane < 16) out[(size_t)node * OUTC + c] = acc / (ssum + EPSV) + b2[c];
}

// ---------------- launch ----------------
extern "C" void kernel_launch(void* const* d_in, const int* in_sizes, int n_in,
                              void* d_out, int out_size) {
    const float* x     = (const float*)d_in[0];
    const int*   ei    = (const int*)d_in[1];
    const float* W1    = (const float*)d_in[2];
    const float* atts1 = (const float*)d_in[3];
    const float* attd1 = (const float*)d_in[4];
    const float* b1    = (const float*)d_in[5];
    const float* W2    = (const float*)d_in[6];
    const float* atts2 = (const float*)d_in[7];
    const float* attd2 = (const float*)d_in[8];
    const float* b2    = (const float*)d_in[9];
    float* out = (float*)d_out;

    zero_deg_kernel<<<64, 256>>>();
    hist_kernel<<<(EE + 255) / 256, 256>>>(ei);
    prep_x_kernel<<<(NN * INC + 255) / 256, 256>>>(x);
    prep_w_kernel<<<(INC * C1 + 255) / 256, 256>>>(W1);
    scan_kernel<<<1, 1024>>>();
    scatter_kernel<<<(EE + 255) / 256, 256>>>(ei);

    gemm1_mma_kernel<<<dim3((NN + 127) / 128, 4), 256>>>(atts1, attd1);
    agg1_kernel<<<(NN + 7) / 8, 256>>>(b1);
    gemm2_kernel<<<(NN + 15) / 16, 256>>>(W2, atts2, attd2);
    agg2_kernel<<<(NN + 7) / 8, 256>>>(b2, out);
}